// round 5
// baseline (speedup 1.0000x reference)
#include <cuda_runtime.h>
#include <math.h>
#include <stdint.h>

// Problem constants (fixed by the dataset)
#define Nn 100000
#define Ee 1600000
#define NE_TOT (Ee + Nn)          // edges + self loops
#define F1 64                     // heads*hid  (8*8)
#define F2 128                    // heads*out  (8*16)
#define IN_CH 512
#define NEG_SLOPE 0.2f

// ---------------- device scratch (static allocation: allowed) ----------------
__device__ int   g_is64;          // 1 if edge_index is int64, 0 if int32
__device__ int   g_count[Nn];
__device__ int   g_offsets[Nn + 1];
__device__ int   g_bsum[128];
__device__ int   g_cursor[Nn];
__device__ int   g_col[NE_TOT];
__device__ __align__(16) float g_h1[(size_t)Nn * F1];     // gemm1 output
__device__ __align__(16) float g_h1act[(size_t)Nn * F1];  // layer1 aggregated + elu
__device__ __align__(16) float g_h2[(size_t)Nn * F2];     // gemm2 output

// ============================ dtype detection ===============================
// JAX without x64 silently downcasts int64 -> int32. Detect which layout the
// harness actually gave us: read the first 64 values as int64; if ALL are in
// [0, Nn) the data is真 int64 (an int32 buffer read as int64 has a random
// nonzero high word with overwhelming probability).
__global__ void k_detect(const void* ei) {
    const long long* p = (const long long*)ei;
    int ok = 1;
    for (int i = 0; i < 64; i++) {
        long long v = p[i];
        if (v < 0 || v >= Nn) { ok = 0; break; }
    }
    g_is64 = ok;
}

__device__ __forceinline__ int load_idx(const void* ei, size_t pos, int is64) {
    return is64 ? (int)((const long long*)ei)[pos] : ((const int*)ei)[pos];
}

// ============================ CSR build =====================================
__global__ void k_init_count() {
    int i = blockIdx.x * blockDim.x + threadIdx.x;
    if (i < Nn) g_count[i] = 1;   // self loop
}

__global__ void k_count(const void* __restrict__ ei) {
    int e = blockIdx.x * blockDim.x + threadIdx.x;
    if (e < Ee) {
        int is64 = g_is64;
        int dst = load_idx(ei, (size_t)Ee + e, is64);
        if ((unsigned)dst < (unsigned)Nn)
            atomicAdd(&g_count[dst], 1);
    }
}

// Block scan: 256 threads x 4 items = 1024 nodes per block. Warp shfl scans.
__global__ void k_scan1() {
    __shared__ int warpsum[8];
    int t = threadIdx.x;                  // 0..255
    int lane = t & 31;
    int wid = t >> 5;
    int base = blockIdx.x * 1024 + t * 4;

    int c0 = (base + 0 < Nn) ? g_count[base + 0] : 0;
    int c1 = (base + 1 < Nn) ? g_count[base + 1] : 0;
    int c2 = (base + 2 < Nn) ? g_count[base + 2] : 0;
    int c3 = (base + 3 < Nn) ? g_count[base + 3] : 0;
    int tot = c0 + c1 + c2 + c3;

    // inclusive warp scan of tot
    int v = tot;
#pragma unroll
    for (int off = 1; off < 32; off <<= 1) {
        int n = __shfl_up_sync(0xffffffffu, v, off);
        if (lane >= off) v += n;
    }
    if (lane == 31) warpsum[wid] = v;
    __syncthreads();
    if (t == 0) {
        int run = 0;
#pragma unroll
        for (int i = 0; i < 8; i++) { int x = warpsum[i]; warpsum[i] = run; run += x; }
    }
    __syncthreads();

    int exc = warpsum[wid] + (v - tot);   // exclusive prefix of this thread's 1st item
    if (base + 0 < Nn) g_offsets[base + 0] = exc;
    exc += c0;
    if (base + 1 < Nn) g_offsets[base + 1] = exc;
    exc += c1;
    if (base + 2 < Nn) g_offsets[base + 2] = exc;
    exc += c2;
    if (base + 3 < Nn) g_offsets[base + 3] = exc;

    if (t == 255) g_bsum[blockIdx.x] = warpsum[7] + v;   // block total
}

// Single-warp scan over the 98 block sums.
__global__ void k_scan2() {
    int lane = threadIdx.x;   // <<<1,32>>>
    int run = 0;
#pragma unroll
    for (int c = 0; c < 4; c++) {
        int idx = c * 32 + lane;
        int x = (idx < 98) ? g_bsum[idx] : 0;
        int v = x;
#pragma unroll
        for (int off = 1; off < 32; off <<= 1) {
            int n = __shfl_up_sync(0xffffffffu, v, off);
            if (lane >= off) v += n;
        }
        if (idx < 98) g_bsum[idx] = run + (v - x);   // exclusive
        run += __shfl_sync(0xffffffffu, v, 31);
    }
}

__global__ void k_scan3() {
    int g = blockIdx.x * blockDim.x + threadIdx.x;
    if (g < Nn) {
        int o = g_offsets[g] + g_bsum[g >> 10];
        g_offsets[g] = o;
        g_cursor[g] = o;
    }
    if (g == 0) g_offsets[Nn] = NE_TOT;
}

__global__ void k_fill(const void* __restrict__ ei) {
    int t = blockIdx.x * blockDim.x + threadIdx.x;
    if (t >= NE_TOT) return;
    if (t < Ee) {
        int is64 = g_is64;
        int src = load_idx(ei, (size_t)t, is64);
        int dst = load_idx(ei, (size_t)Ee + t, is64);
        if ((unsigned)src < (unsigned)Nn && (unsigned)dst < (unsigned)Nn) {
            int pos = atomicAdd(&g_cursor[dst], 1);
            if ((unsigned)pos < (unsigned)NE_TOT) g_col[pos] = src;
        }
    } else {
        int i = t - Ee;
        int pos = atomicAdd(&g_cursor[i], 1);
        if ((unsigned)pos < (unsigned)NE_TOT) g_col[pos] = i;   // self loop
    }
}

// ============================ GEMM 1: x[N,512] @ W1[512,64] =================
// block tile 128 rows x 64 cols, 256 threads, thread tile 8x4
__global__ void k_gemm1(const float* __restrict__ x, const float* __restrict__ W) {
    __shared__ float As[32][129];   // [k][row]  (pad 129 -> conflict-free scatter stores)
    __shared__ float Bs[32][68];    // [k][col]

    int tid = threadIdx.x;
    int row0 = blockIdx.x * 128;
    int ry = tid >> 4;      // 0..15 -> rows ry*8..ry*8+7
    int cx = tid & 15;      // 0..15 -> cols cx*4..cx*4+3

    float acc[8][4];
#pragma unroll
    for (int r = 0; r < 8; r++)
#pragma unroll
        for (int c = 0; c < 4; c++) acc[r][c] = 0.f;

    for (int k0 = 0; k0 < IN_CH; k0 += 32) {
        // load A tile: 128 rows x 32 k
#pragma unroll
        for (int it = 0; it < 4; it++) {
            int s = it * 256 + tid;      // 0..1023
            int r = s >> 3;              // 0..127
            int kq = s & 7;              // 0..7 (x4 floats)
            int grow = row0 + r;
            float4 v = make_float4(0.f, 0.f, 0.f, 0.f);
            if (grow < Nn)
                v = *reinterpret_cast<const float4*>(x + (size_t)grow * IN_CH + k0 + kq * 4);
            As[kq * 4 + 0][r] = v.x;
            As[kq * 4 + 1][r] = v.y;
            As[kq * 4 + 2][r] = v.z;
            As[kq * 4 + 3][r] = v.w;
        }
        // load B tile: 32 k x 64 cols
#pragma unroll
        for (int it = 0; it < 2; it++) {
            int s = it * 256 + tid;      // 0..511
            int kk = s >> 4;             // 0..31
            int cq = s & 15;             // 0..15 (x4 floats)
            float4 v = *reinterpret_cast<const float4*>(W + (size_t)(k0 + kk) * F1 + cq * 4);
            *reinterpret_cast<float4*>(&Bs[kk][cq * 4]) = v;
        }
        __syncthreads();

#pragma unroll
        for (int k = 0; k < 32; k++) {
            float a[8];
#pragma unroll
            for (int j = 0; j < 8; j++) a[j] = As[k][ry * 8 + j];
            float4 bv = *reinterpret_cast<const float4*>(&Bs[k][cx * 4]);
            float b[4] = {bv.x, bv.y, bv.z, bv.w};
#pragma unroll
            for (int r = 0; r < 8; r++)
#pragma unroll
                for (int c = 0; c < 4; c++) acc[r][c] = fmaf(a[r], b[c], acc[r][c]);
        }
        __syncthreads();
    }

#pragma unroll
    for (int r = 0; r < 8; r++) {
        int grow = row0 + ry * 8 + r;
        if (grow < Nn) {
            float4 v = make_float4(acc[r][0], acc[r][1], acc[r][2], acc[r][3]);
            *reinterpret_cast<float4*>(&g_h1[(size_t)grow * F1 + cx * 4]) = v;
        }
    }
}

// ============================ GEMM 2: h1act[N,64] @ W2[64,128] ==============
// block tile 64 rows x 128 cols, 256 threads, thread tile 4x8.
// B loaded in two 32-K chunks to stay under the 48KB static smem limit.
__global__ void k_gemm2(const float* __restrict__ W) {
    __shared__ float As[64][65];    // [k][row]   16640 B
    __shared__ float Bs[32][132];   // [k][col]   16896 B  (total 33536 B)

    int tid = threadIdx.x;
    int row0 = blockIdx.x * 64;
    int ry = tid >> 4;   // 0..15 -> rows ry*4..+3
    int cx = tid & 15;   // 0..15 -> cols cx*8..+7

    // load A: 64 rows x 64 k (once)
#pragma unroll
    for (int it = 0; it < 4; it++) {
        int s = it * 256 + tid;   // 0..1023
        int r = s >> 4;           // 0..63
        int kq = s & 15;          // 0..15 (x4)
        int grow = row0 + r;
        float4 v = make_float4(0.f, 0.f, 0.f, 0.f);
        if (grow < Nn)
            v = *reinterpret_cast<const float4*>(&g_h1act[(size_t)grow * F1 + kq * 4]);
        As[kq * 4 + 0][r] = v.x;
        As[kq * 4 + 1][r] = v.y;
        As[kq * 4 + 2][r] = v.z;
        As[kq * 4 + 3][r] = v.w;
    }

    float acc[4][8];
#pragma unroll
    for (int r = 0; r < 4; r++)
#pragma unroll
        for (int c = 0; c < 8; c++) acc[r][c] = 0.f;

    for (int kc = 0; kc < 64; kc += 32) {
        // load B chunk: 32 k x 128 cols
#pragma unroll
        for (int it = 0; it < 4; it++) {
            int s = it * 256 + tid;   // 0..1023
            int kk = s >> 5;          // 0..31
            int cq = s & 31;          // 0..31 (x4)
            float4 v = *reinterpret_cast<const float4*>(W + (size_t)(kc + kk) * F2 + cq * 4);
            *reinterpret_cast<float4*>(&Bs[kk][cq * 4]) = v;
        }
        __syncthreads();

#pragma unroll
        for (int k = 0; k < 32; k++) {
            float a[4];
#pragma unroll
            for (int j = 0; j < 4; j++) a[j] = As[kc + k][ry * 4 + j];
            float4 b0 = *reinterpret_cast<const float4*>(&Bs[k][cx * 8]);
            float4 b1 = *reinterpret_cast<const float4*>(&Bs[k][cx * 8 + 4]);
            float b[8] = {b0.x, b0.y, b0.z, b0.w, b1.x, b1.y, b1.z, b1.w};
#pragma unroll
            for (int r = 0; r < 4; r++)
#pragma unroll
                for (int c = 0; c < 8; c++) acc[r][c] = fmaf(a[r], b[c], acc[r][c]);
        }
        __syncthreads();
    }

#pragma unroll
    for (int r = 0; r < 4; r++) {
        int grow = row0 + ry * 4 + r;
        if (grow < Nn) {
            float4 v0 = make_float4(acc[r][0], acc[r][1], acc[r][2], acc[r][3]);
            float4 v1 = make_float4(acc[r][4], acc[r][5], acc[r][6], acc[r][7]);
            *reinterpret_cast<float4*>(&g_h2[(size_t)grow * F2 + cx * 8]) = v0;
            *reinterpret_cast<float4*>(&g_h2[(size_t)grow * F2 + cx * 8 + 4]) = v1;
        }
    }
}

// ============================ fused edge softmax-aggregate ==================
// One warp per destination node; lane = head*4 + q; lane owns PL=F/32 channels.
// Online softmax over in-edges -> no atomics, no alpha scratch, single gather.
template <int C, bool FINAL>
__global__ void k_edge(const float* __restrict__ attl,
                       const float* __restrict__ attr,
                       const float* __restrict__ bias,
                       float* __restrict__ outFinal) {
    constexpr int F = 8 * C;
    constexpr int PL = F / 32;   // 2 (layer1) or 4 (layer2)

    int warp = (blockIdx.x * blockDim.x + threadIdx.x) >> 5;
    if (warp >= Nn) return;
    int i = warp;
    int lane = threadIdx.x & 31;
    int head = lane >> 2;
    int q = lane & 3;

    const float* __restrict__ h = FINAL ? (const float*)g_h2 : (const float*)g_h1;
    float* __restrict__ o = FINAL ? outFinal : g_h1act;

    float wl[PL], xi[PL];
    float ar = 0.f;
#pragma unroll
    for (int p = 0; p < PL; p++) {
        int c = q * PL + p;
        wl[p] = attl[head * C + c];
        float wr = attr[head * C + c];
        xi[p] = h[(size_t)i * F + lane * PL + p];
        ar += xi[p] * wr;
    }
    ar += __shfl_xor_sync(0xffffffffu, ar, 1);
    ar += __shfl_xor_sync(0xffffffffu, ar, 2);

    int e0 = g_offsets[i];
    int e1 = g_offsets[i + 1];

    float m = __int_as_float(0xff800000);   // -inf
    float d = 0.f;
    float acc[PL];
#pragma unroll
    for (int p = 0; p < PL; p++) acc[p] = 0.f;

    for (int e = e0; e < e1; e++) {
        int src = g_col[e];
        float xj[PL];
        const float* hp = h + (size_t)src * F + lane * PL;
        if constexpr (PL == 2) {
            float2 v = *reinterpret_cast<const float2*>(hp);
            xj[0] = v.x; xj[1] = v.y;
        } else {
            float4 v = *reinterpret_cast<const float4*>(hp);
            xj[0] = v.x; xj[1] = v.y; xj[2] = v.z; xj[3] = v.w;
        }
        float lg = 0.f, al = 0.f;
#pragma unroll
        for (int p = 0; p < PL; p++) {
            lg = fmaf(xi[p], xj[p], lg);
            al = fmaf(wl[p], xj[p], al);
        }
        lg += __shfl_xor_sync(0xffffffffu, lg, 1);
        al += __shfl_xor_sync(0xffffffffu, al, 1);
        lg += __shfl_xor_sync(0xffffffffu, lg, 2);
        al += __shfl_xor_sync(0xffffffffu, al, 2);

        float sig = 1.f / (1.f + __expf(-lg));
        float a = (al + ar) * sig;
        a = (a > 0.f) ? a : NEG_SLOPE * a;

        float mnew = fmaxf(m, a);
        float corr = __expf(m - mnew);      // 0 on first edge (m = -inf)
        float w = __expf(a - mnew);
        d = d * corr + w;
#pragma unroll
        for (int p = 0; p < PL; p++) acc[p] = acc[p] * corr + w * xj[p];
        m = mnew;
    }

    float inv = 1.f / (d + 1e-16f);

    if constexpr (!FINAL) {
        // + b1, ELU, write h1act
#pragma unroll
        for (int p = 0; p < PL; p++) {
            float v = acc[p] * inv + bias[lane * PL + p];
            v = (v > 0.f) ? v : expm1f(v);
            o[(size_t)i * F + lane * PL + p] = v;
        }
    } else {
        // mean over heads, + b2, log_softmax over 16 channels
        float v[PL];
#pragma unroll
        for (int p = 0; p < PL; p++) {
            float s = acc[p] * inv;
            s += __shfl_xor_sync(0xffffffffu, s, 4);
            s += __shfl_xor_sync(0xffffffffu, s, 8);
            s += __shfl_xor_sync(0xffffffffu, s, 16);
            v[p] = s * 0.125f + bias[q * PL + p];
        }
        float mx = v[0];
#pragma unroll
        for (int p = 1; p < PL; p++) mx = fmaxf(mx, v[p]);
        mx = fmaxf(mx, __shfl_xor_sync(0xffffffffu, mx, 1));
        mx = fmaxf(mx, __shfl_xor_sync(0xffffffffu, mx, 2));
        float se = 0.f;
#pragma unroll
        for (int p = 0; p < PL; p++) se += __expf(v[p] - mx);
        se += __shfl_xor_sync(0xffffffffu, se, 1);
        se += __shfl_xor_sync(0xffffffffu, se, 2);
        float lse = mx + logf(se);
        if (lane < 4) {
#pragma unroll
            for (int p = 0; p < PL; p++)
                o[(size_t)i * 16 + q * PL + p] = v[p] - lse;
        }
    }
}

// ============================ launch ========================================
extern "C" void kernel_launch(void* const* d_in, const int* in_sizes, int n_in,
                              void* d_out, int out_size) {
    (void)in_sizes; (void)n_in; (void)out_size;
    const float* x     = (const float*)d_in[0];
    const void*  ei    = d_in[1];             // int64 OR int32 (detected on device)
    const float* W1    = (const float*)d_in[2];
    const float* attl1 = (const float*)d_in[3];
    const float* attr1 = (const float*)d_in[4];
    const float* b1    = (const float*)d_in[5];
    const float* W2    = (const float*)d_in[6];
    const float* attl2 = (const float*)d_in[7];
    const float* attr2 = (const float*)d_in[8];
    const float* b2    = (const float*)d_in[9];
    float* out = (float*)d_out;

    // CSR build
    k_detect<<<1, 1>>>(ei);
    k_init_count<<<(Nn + 255) / 256, 256>>>();
    k_count<<<(Ee + 255) / 256, 256>>>(ei);
    k_scan1<<<98, 256>>>();
    k_scan2<<<1, 32>>>();
    k_scan3<<<(Nn + 255) / 256, 256>>>();
    k_fill<<<(NE_TOT + 255) / 256, 256>>>(ei);

    // Layer 1
    k_gemm1<<<(Nn + 127) / 128, 256>>>(x, W1);
    k_edge<8, false><<<(Nn + 7) / 8, 256>>>(attl1, attr1, b1, nullptr);

    // Layer 2
    k_gemm2<<<(Nn + 63) / 64, 256>>>(W2);
    k_edge<16, true><<<(Nn + 7) / 8, 256>>>(attl2, attr2, b2, out);
}

// round 6
// speedup vs baseline: 1.0838x; 1.0838x over previous
#include <cuda_runtime.h>
#include <math.h>
#include <stdint.h>

// Problem constants (fixed by the dataset)
#define Nn 100000
#define Ee 1600000
#define NE_TOT (Ee + Nn)          // edges + self loops
#define F1 64                     // heads*hid  (8*8)
#define F2 128                    // heads*out  (8*16)
#define IN_CH 512
#define NEG_SLOPE 0.2f

// ---------------- device scratch (static allocation: allowed) ----------------
__device__ int   g_is64;          // 1 if edge_index is int64, 0 if int32
__device__ int   g_count[Nn];
__device__ int   g_offsets[Nn + 1];
__device__ int   g_bsum[128];
__device__ int   g_cursor[Nn];
__device__ int   g_col[NE_TOT];
__device__ __align__(16) float g_h1[(size_t)Nn * F1];     // gemm1 output
__device__ __align__(16) float g_h1act[(size_t)Nn * F1];  // layer1 aggregated + elu
__device__ __align__(16) float g_h2[(size_t)Nn * F2];     // gemm2 output

// ---------------- packed fp32x2 helpers (Blackwell FFMA2) -------------------
__device__ __forceinline__ unsigned long long pack2(float lo, float hi) {
    unsigned long long r;
    asm("mov.b64 %0, {%1, %2};" : "=l"(r) : "f"(lo), "f"(hi));
    return r;
}
__device__ __forceinline__ void ffma2(unsigned long long &d, unsigned long long a,
                                      unsigned long long b) {
    asm("fma.rn.f32x2 %0, %1, %2, %0;" : "+l"(d) : "l"(a), "l"(b));
}
__device__ __forceinline__ void unpack2(unsigned long long v, float &lo, float &hi) {
    asm("mov.b64 {%0, %1}, %2;" : "=f"(lo), "=f"(hi) : "l"(v));
}

// ============================ dtype detection ===============================
// JAX without x64 silently downcasts int64 -> int32. Detect which layout the
// harness actually gave us.
__global__ void k_detect(const void* ei) {
    const long long* p = (const long long*)ei;
    int ok = 1;
    for (int i = 0; i < 64; i++) {
        long long v = p[i];
        if (v < 0 || v >= Nn) { ok = 0; break; }
    }
    g_is64 = ok;
}

__device__ __forceinline__ int load_idx(const void* ei, size_t pos, int is64) {
    return is64 ? (int)((const long long*)ei)[pos] : ((const int*)ei)[pos];
}

// ============================ CSR build =====================================
__global__ void k_init_count() {
    int i = blockIdx.x * blockDim.x + threadIdx.x;
    if (i < Nn) g_count[i] = 1;   // self loop
}

__global__ void k_count(const void* __restrict__ ei) {
    int e = blockIdx.x * blockDim.x + threadIdx.x;
    if (e < Ee) {
        int is64 = g_is64;
        int dst = load_idx(ei, (size_t)Ee + e, is64);
        if ((unsigned)dst < (unsigned)Nn)
            atomicAdd(&g_count[dst], 1);
    }
}

// Block scan: 256 threads x 4 items = 1024 nodes per block. Warp shfl scans.
__global__ void k_scan1() {
    __shared__ int warpsum[8];
    int t = threadIdx.x;                  // 0..255
    int lane = t & 31;
    int wid = t >> 5;
    int base = blockIdx.x * 1024 + t * 4;

    int c0 = (base + 0 < Nn) ? g_count[base + 0] : 0;
    int c1 = (base + 1 < Nn) ? g_count[base + 1] : 0;
    int c2 = (base + 2 < Nn) ? g_count[base + 2] : 0;
    int c3 = (base + 3 < Nn) ? g_count[base + 3] : 0;
    int tot = c0 + c1 + c2 + c3;

    int v = tot;
#pragma unroll
    for (int off = 1; off < 32; off <<= 1) {
        int n = __shfl_up_sync(0xffffffffu, v, off);
        if (lane >= off) v += n;
    }
    if (lane == 31) warpsum[wid] = v;
    __syncthreads();
    if (t == 0) {
        int run = 0;
#pragma unroll
        for (int i = 0; i < 8; i++) { int x = warpsum[i]; warpsum[i] = run; run += x; }
    }
    __syncthreads();

    int exc = warpsum[wid] + (v - tot);
    if (base + 0 < Nn) g_offsets[base + 0] = exc;
    exc += c0;
    if (base + 1 < Nn) g_offsets[base + 1] = exc;
    exc += c1;
    if (base + 2 < Nn) g_offsets[base + 2] = exc;
    exc += c2;
    if (base + 3 < Nn) g_offsets[base + 3] = exc;

    if (t == 255) g_bsum[blockIdx.x] = warpsum[7] + v;
}

__global__ void k_scan2() {
    int lane = threadIdx.x;   // <<<1,32>>>
    int run = 0;
#pragma unroll
    for (int c = 0; c < 4; c++) {
        int idx = c * 32 + lane;
        int x = (idx < 98) ? g_bsum[idx] : 0;
        int v = x;
#pragma unroll
        for (int off = 1; off < 32; off <<= 1) {
            int n = __shfl_up_sync(0xffffffffu, v, off);
            if (lane >= off) v += n;
        }
        if (idx < 98) g_bsum[idx] = run + (v - x);
        run += __shfl_sync(0xffffffffu, v, 31);
    }
}

__global__ void k_scan3() {
    int g = blockIdx.x * blockDim.x + threadIdx.x;
    if (g < Nn) {
        int o = g_offsets[g] + g_bsum[g >> 10];
        g_offsets[g] = o;
        g_cursor[g] = o;
    }
    if (g == 0) g_offsets[Nn] = NE_TOT;
}

__global__ void k_fill(const void* __restrict__ ei) {
    int t = blockIdx.x * blockDim.x + threadIdx.x;
    if (t >= NE_TOT) return;
    if (t < Ee) {
        int is64 = g_is64;
        int src = load_idx(ei, (size_t)t, is64);
        int dst = load_idx(ei, (size_t)Ee + t, is64);
        if ((unsigned)src < (unsigned)Nn && (unsigned)dst < (unsigned)Nn) {
            int pos = atomicAdd(&g_cursor[dst], 1);
            if ((unsigned)pos < (unsigned)NE_TOT) g_col[pos] = src;
        }
    } else {
        int i = t - Ee;
        int pos = atomicAdd(&g_cursor[i], 1);
        if ((unsigned)pos < (unsigned)NE_TOT) g_col[pos] = i;   // self loop
    }
}

// ============================ GEMM 1: x[N,512] @ W1[512,64] =================
// block tile 128 rows x 64 cols, 128 threads, thread tile 8x8, FFMA2 packed.
__global__ __launch_bounds__(128) void k_gemm1(const float* __restrict__ x,
                                               const float* __restrict__ W) {
    __shared__ float As[32][132];   // [k][row], pad 132 (16B-aligned rows)
    __shared__ float Bs[32][68];    // [k][col]

    int tid = threadIdx.x;
    int row0 = blockIdx.x * 128;
    int ry = tid >> 3;      // 0..15 -> rows ry*8..+7
    int cx = tid & 7;       // 0..7  -> cols cx*8..+7

    unsigned long long acc[8][4];   // 8 rows x 4 col-pairs
#pragma unroll
    for (int r = 0; r < 8; r++)
#pragma unroll
        for (int c = 0; c < 4; c++) acc[r][c] = 0ull;

    for (int k0 = 0; k0 < IN_CH; k0 += 32) {
        // load A tile: 128 rows x 32 k  (1024 float4, 8 per thread)
#pragma unroll
        for (int it = 0; it < 8; it++) {
            int s = it * 128 + tid;
            int r = s >> 3;              // 0..127
            int kq = s & 7;              // 0..7 (x4 floats)
            int grow = row0 + r;
            float4 v = make_float4(0.f, 0.f, 0.f, 0.f);
            if (grow < Nn)
                v = *reinterpret_cast<const float4*>(x + (size_t)grow * IN_CH + k0 + kq * 4);
            As[kq * 4 + 0][r] = v.x;
            As[kq * 4 + 1][r] = v.y;
            As[kq * 4 + 2][r] = v.z;
            As[kq * 4 + 3][r] = v.w;
        }
        // load B tile: 32 k x 64 cols (512 float4, 4 per thread)
#pragma unroll
        for (int it = 0; it < 4; it++) {
            int s = it * 128 + tid;
            int kk = s >> 4;             // 0..31
            int cq = s & 15;             // 0..15
            float4 v = *reinterpret_cast<const float4*>(W + (size_t)(k0 + kk) * F1 + cq * 4);
            *reinterpret_cast<float4*>(&Bs[kk][cq * 4]) = v;
        }
        __syncthreads();

#pragma unroll 8
        for (int k = 0; k < 32; k++) {
            float4 a0 = *reinterpret_cast<const float4*>(&As[k][ry * 8]);
            float4 a1 = *reinterpret_cast<const float4*>(&As[k][ry * 8 + 4]);
            float4 b0 = *reinterpret_cast<const float4*>(&Bs[k][cx * 8]);
            float4 b1 = *reinterpret_cast<const float4*>(&Bs[k][cx * 8 + 4]);
            unsigned long long bp[4] = { pack2(b0.x, b0.y), pack2(b0.z, b0.w),
                                         pack2(b1.x, b1.y), pack2(b1.z, b1.w) };
            float av[8] = {a0.x, a0.y, a0.z, a0.w, a1.x, a1.y, a1.z, a1.w};
#pragma unroll
            for (int r = 0; r < 8; r++) {
                unsigned long long ap = pack2(av[r], av[r]);
#pragma unroll
                for (int c = 0; c < 4; c++) ffma2(acc[r][c], ap, bp[c]);
            }
        }
        __syncthreads();
    }

#pragma unroll
    for (int r = 0; r < 8; r++) {
        int grow = row0 + ry * 8 + r;
        if (grow < Nn) {
            float o[8];
#pragma unroll
            for (int c = 0; c < 4; c++) unpack2(acc[r][c], o[c * 2], o[c * 2 + 1]);
            float* dst = &g_h1[(size_t)grow * F1 + cx * 8];
            *reinterpret_cast<float4*>(dst)     = make_float4(o[0], o[1], o[2], o[3]);
            *reinterpret_cast<float4*>(dst + 4) = make_float4(o[4], o[5], o[6], o[7]);
        }
    }
}

// ============================ GEMM 2: h1act[N,64] @ W2[64,128] ==============
// block tile 64 rows x 128 cols, 256 threads, thread tile 4x8.
__global__ void k_gemm2(const float* __restrict__ W) {
    __shared__ float As[64][65];    // [k][row]   16640 B
    __shared__ float Bs[32][132];   // [k][col]   16896 B

    int tid = threadIdx.x;
    int row0 = blockIdx.x * 64;
    int ry = tid >> 4;   // 0..15 -> rows ry*4..+3
    int cx = tid & 15;   // 0..15 -> cols cx*8..+7

#pragma unroll
    for (int it = 0; it < 4; it++) {
        int s = it * 256 + tid;
        int r = s >> 4;           // 0..63
        int kq = s & 15;          // 0..15
        int grow = row0 + r;
        float4 v = make_float4(0.f, 0.f, 0.f, 0.f);
        if (grow < Nn)
            v = *reinterpret_cast<const float4*>(&g_h1act[(size_t)grow * F1 + kq * 4]);
        As[kq * 4 + 0][r] = v.x;
        As[kq * 4 + 1][r] = v.y;
        As[kq * 4 + 2][r] = v.z;
        As[kq * 4 + 3][r] = v.w;
    }

    float acc[4][8];
#pragma unroll
    for (int r = 0; r < 4; r++)
#pragma unroll
        for (int c = 0; c < 8; c++) acc[r][c] = 0.f;

    for (int kc = 0; kc < 64; kc += 32) {
#pragma unroll
        for (int it = 0; it < 4; it++) {
            int s = it * 256 + tid;
            int kk = s >> 5;          // 0..31
            int cq = s & 31;          // 0..31
            float4 v = *reinterpret_cast<const float4*>(W + (size_t)(kc + kk) * F2 + cq * 4);
            *reinterpret_cast<float4*>(&Bs[kk][cq * 4]) = v;
        }
        __syncthreads();

#pragma unroll
        for (int k = 0; k < 32; k++) {
            float a[4];
#pragma unroll
            for (int j = 0; j < 4; j++) a[j] = As[kc + k][ry * 4 + j];
            float4 b0 = *reinterpret_cast<const float4*>(&Bs[k][cx * 8]);
            float4 b1 = *reinterpret_cast<const float4*>(&Bs[k][cx * 8 + 4]);
            float b[8] = {b0.x, b0.y, b0.z, b0.w, b1.x, b1.y, b1.z, b1.w};
#pragma unroll
            for (int r = 0; r < 4; r++)
#pragma unroll
                for (int c = 0; c < 8; c++) acc[r][c] = fmaf(a[r], b[c], acc[r][c]);
        }
        __syncthreads();
    }

#pragma unroll
    for (int r = 0; r < 4; r++) {
        int grow = row0 + ry * 4 + r;
        if (grow < Nn) {
            float4 v0 = make_float4(acc[r][0], acc[r][1], acc[r][2], acc[r][3]);
            float4 v1 = make_float4(acc[r][4], acc[r][5], acc[r][6], acc[r][7]);
            *reinterpret_cast<float4*>(&g_h2[(size_t)grow * F2 + cx * 8]) = v0;
            *reinterpret_cast<float4*>(&g_h2[(size_t)grow * F2 + cx * 8 + 4]) = v1;
        }
    }
}

// ============================ fused edge softmax-aggregate ==================
// Lane-owns-head layout: lane = sub*8 + head; 4 nodes per warp, each lane owns
// a full head's C channels -> per-head dots are LOCAL, zero shuffles per edge.
// Online softmax per (node, head) entirely in one lane's registers.
template <int C, bool FINAL>
__global__ __launch_bounds__(256) void k_edge(const float* __restrict__ attl,
                                              const float* __restrict__ attr,
                                              const float* __restrict__ bias,
                                              float* __restrict__ outFinal) {
    constexpr int F = 8 * C;

    int warp = (blockIdx.x * blockDim.x + threadIdx.x) >> 5;
    int lane = threadIdx.x & 31;
    int sub  = lane >> 3;     // node slot within warp (0..3)
    int head = lane & 7;      // head owned by this lane
    int i = warp * 4 + sub;
    if (i >= Nn) return;      // never taken: 3125*256 threads = exactly 100000 nodes

    const float* __restrict__ h = FINAL ? (const float*)g_h2 : (const float*)g_h1;

    float xi[C], wl[C], acc[C];
    float ar = 0.f;
    const float* hi = h + (size_t)i * F + head * C;
#pragma unroll
    for (int c4 = 0; c4 < C; c4 += 4) {
        float4 v = *reinterpret_cast<const float4*>(hi + c4);
        xi[c4 + 0] = v.x; xi[c4 + 1] = v.y; xi[c4 + 2] = v.z; xi[c4 + 3] = v.w;
    }
#pragma unroll
    for (int c = 0; c < C; c++) {
        wl[c] = attl[head * C + c];
        ar = fmaf(xi[c], attr[head * C + c], ar);
        acc[c] = 0.f;
    }

    int e0 = g_offsets[i];
    int e1 = g_offsets[i + 1];

    float m = __int_as_float(0xff800000);   // -inf
    float d = 0.f;

    int src = g_col[e0];
    for (int e = e0; e < e1; ) {
        const float* hj = h + (size_t)src * F + head * C;
        float xj[C];
#pragma unroll
        for (int c4 = 0; c4 < C; c4 += 4) {
            float4 v = *reinterpret_cast<const float4*>(hj + c4);
            xj[c4 + 0] = v.x; xj[c4 + 1] = v.y; xj[c4 + 2] = v.z; xj[c4 + 3] = v.w;
        }
        e++;
        if (e < e1) src = g_col[e];   // prefetch next src index

        float lg = 0.f, al = 0.f;
#pragma unroll
        for (int c = 0; c < C; c++) {
            lg = fmaf(xi[c], xj[c], lg);
            al = fmaf(wl[c], xj[c], al);
        }
        float sig = 1.f / (1.f + __expf(-lg));
        float a = (al + ar) * sig;
        a = (a > 0.f) ? a : NEG_SLOPE * a;

        float mn = fmaxf(m, a);
        float corr = __expf(m - mn);          // 0 on first edge (m = -inf)
        float w = __expf(a - mn);
        d = d * corr + w;
#pragma unroll
        for (int c = 0; c < C; c++) acc[c] = fmaf(acc[c], corr, w * xj[c]);
        m = mn;
    }

    float inv = 1.f / (d + 1e-16f);

    if constexpr (!FINAL) {
        // + b1, ELU, write h1act (lane writes its head's C channels, coalesced)
        float* o = g_h1act + (size_t)i * F + head * C;
#pragma unroll
        for (int c4 = 0; c4 < C; c4 += 4) {
            float v[4];
#pragma unroll
            for (int j = 0; j < 4; j++) {
                float t = acc[c4 + j] * inv + bias[head * C + c4 + j];
                v[j] = (t > 0.f) ? t : expm1f(t);
            }
            *reinterpret_cast<float4*>(o + c4) = make_float4(v[0], v[1], v[2], v[3]);
        }
    } else {
        // mean over 8 heads (xor-reduce within the 8-lane subgroup), + b2,
        // then log_softmax over the 16 channels (local to each lane).
        float v[C];
#pragma unroll
        for (int c = 0; c < C; c++) {
            float s = acc[c] * inv;
            s += __shfl_xor_sync(0xffffffffu, s, 1);
            s += __shfl_xor_sync(0xffffffffu, s, 2);
            s += __shfl_xor_sync(0xffffffffu, s, 4);
            v[c] = s * 0.125f + bias[c];
        }
        if (head == 0) {
            float mx = v[0];
#pragma unroll
            for (int c = 1; c < C; c++) mx = fmaxf(mx, v[c]);
            float se = 0.f;
#pragma unroll
            for (int c = 0; c < C; c++) se += __expf(v[c] - mx);
            float lse = mx + logf(se);
            float* o = outFinal + (size_t)i * 16;
#pragma unroll
            for (int c4 = 0; c4 < C; c4 += 4)
                *reinterpret_cast<float4*>(o + c4) =
                    make_float4(v[c4] - lse, v[c4 + 1] - lse, v[c4 + 2] - lse, v[c4 + 3] - lse);
        }
    }
}

// ============================ launch ========================================
extern "C" void kernel_launch(void* const* d_in, const int* in_sizes, int n_in,
                              void* d_out, int out_size) {
    (void)in_sizes; (void)n_in; (void)out_size;
    const float* x     = (const float*)d_in[0];
    const void*  ei    = d_in[1];             // int64 OR int32 (detected on device)
    const float* W1    = (const float*)d_in[2];
    const float* attl1 = (const float*)d_in[3];
    const float* attr1 = (const float*)d_in[4];
    const float* b1    = (const float*)d_in[5];
    const float* W2    = (const float*)d_in[6];
    const float* attl2 = (const float*)d_in[7];
    const float* attr2 = (const float*)d_in[8];
    const float* b2    = (const float*)d_in[9];
    float* out = (float*)d_out;

    // CSR build
    k_detect<<<1, 1>>>(ei);
    k_init_count<<<(Nn + 255) / 256, 256>>>();
    k_count<<<(Ee + 255) / 256, 256>>>(ei);
    k_scan1<<<98, 256>>>();
    k_scan2<<<1, 32>>>();
    k_scan3<<<(Nn + 255) / 256, 256>>>();
    k_fill<<<(NE_TOT + 255) / 256, 256>>>(ei);

    // Layer 1
    k_gemm1<<<(Nn + 127) / 128, 128>>>(x, W1);
    k_edge<8, false><<<(Nn + 31) / 32, 256>>>(attl1, attr1, b1, nullptr);

    // Layer 2
    k_gemm2<<<(Nn + 63) / 64, 256>>>(W2);
    k_edge<16, true><<<(Nn + 31) / 32, 256>>>(attl2, attr2, b2, out);
}

// round 7
// speedup vs baseline: 1.0997x; 1.0146x over previous
#include <cuda_runtime.h>
#include <math.h>
#include <stdint.h>

// Problem constants (fixed by the dataset)
#define Nn 100000
#define Ee 1600000
#define NE_TOT (Ee + Nn)          // edges + self loops
#define F1 64                     // heads*hid  (8*8)
#define F2 128                    // heads*out  (8*16)
#define IN_CH 512
#define NEG_SLOPE 0.2f

// ---------------- device scratch (static allocation: allowed) ----------------
__device__ int   g_is64;          // 1 if edge_index is int64, 0 if int32
__device__ int   g_count[Nn];
__device__ int   g_offsets[Nn + 1];
__device__ int   g_bsum[128];
__device__ int   g_cursor[Nn];
__device__ int   g_col[NE_TOT + 8];   // +8 pad: prefetch-safe
__device__ __align__(16) float g_h1[(size_t)Nn * F1];     // gemm1 output
__device__ __align__(16) float g_h1act[(size_t)Nn * F1];  // layer1 aggregated + elu
__device__ __align__(16) float g_h2[(size_t)Nn * F2];     // gemm2 output

// ---------------- packed fp32x2 helpers (Blackwell FFMA2) -------------------
__device__ __forceinline__ unsigned long long pack2(float lo, float hi) {
    unsigned long long r;
    asm("mov.b64 %0, {%1, %2};" : "=l"(r) : "f"(lo), "f"(hi));
    return r;
}
__device__ __forceinline__ void ffma2(unsigned long long &d, unsigned long long a,
                                      unsigned long long b) {
    asm("fma.rn.f32x2 %0, %1, %2, %0;" : "+l"(d) : "l"(a), "l"(b));
}
__device__ __forceinline__ void unpack2(unsigned long long v, float &lo, float &hi) {
    asm("mov.b64 {%0, %1}, %2;" : "=f"(lo), "=f"(hi) : "l"(v));
}

// ============================ dtype detection ===============================
__global__ void k_detect(const void* ei) {
    const long long* p = (const long long*)ei;
    int ok = 1;
    for (int i = 0; i < 64; i++) {
        long long v = p[i];
        if (v < 0 || v >= Nn) { ok = 0; break; }
    }
    g_is64 = ok;
}

__device__ __forceinline__ int load_idx(const void* ei, size_t pos, int is64) {
    return is64 ? (int)((const long long*)ei)[pos] : ((const int*)ei)[pos];
}

// ============================ CSR build =====================================
__global__ void k_init_count() {
    int i = blockIdx.x * blockDim.x + threadIdx.x;
    if (i < Nn) g_count[i] = 1;   // self loop
}

__global__ void k_count(const void* __restrict__ ei) {
    int e = blockIdx.x * blockDim.x + threadIdx.x;
    if (e < Ee) {
        int is64 = g_is64;
        int dst = load_idx(ei, (size_t)Ee + e, is64);
        if ((unsigned)dst < (unsigned)Nn)
            atomicAdd(&g_count[dst], 1);
    }
}

// Block scan: 256 threads x 4 items = 1024 nodes per block. Warp shfl scans.
__global__ void k_scan1() {
    __shared__ int warpsum[8];
    int t = threadIdx.x;
    int lane = t & 31;
    int wid = t >> 5;
    int base = blockIdx.x * 1024 + t * 4;

    int c0 = (base + 0 < Nn) ? g_count[base + 0] : 0;
    int c1 = (base + 1 < Nn) ? g_count[base + 1] : 0;
    int c2 = (base + 2 < Nn) ? g_count[base + 2] : 0;
    int c3 = (base + 3 < Nn) ? g_count[base + 3] : 0;
    int tot = c0 + c1 + c2 + c3;

    int v = tot;
#pragma unroll
    for (int off = 1; off < 32; off <<= 1) {
        int n = __shfl_up_sync(0xffffffffu, v, off);
        if (lane >= off) v += n;
    }
    if (lane == 31) warpsum[wid] = v;
    __syncthreads();
    if (t == 0) {
        int run = 0;
#pragma unroll
        for (int i = 0; i < 8; i++) { int x = warpsum[i]; warpsum[i] = run; run += x; }
    }
    __syncthreads();

    int exc = warpsum[wid] + (v - tot);
    if (base + 0 < Nn) g_offsets[base + 0] = exc;
    exc += c0;
    if (base + 1 < Nn) g_offsets[base + 1] = exc;
    exc += c1;
    if (base + 2 < Nn) g_offsets[base + 2] = exc;
    exc += c2;
    if (base + 3 < Nn) g_offsets[base + 3] = exc;

    if (t == 255) g_bsum[blockIdx.x] = warpsum[7] + v;
}

__global__ void k_scan2() {
    int lane = threadIdx.x;   // <<<1,32>>>
    int run = 0;
#pragma unroll
    for (int c = 0; c < 4; c++) {
        int idx = c * 32 + lane;
        int x = (idx < 98) ? g_bsum[idx] : 0;
        int v = x;
#pragma unroll
        for (int off = 1; off < 32; off <<= 1) {
            int n = __shfl_up_sync(0xffffffffu, v, off);
            if (lane >= off) v += n;
        }
        if (idx < 98) g_bsum[idx] = run + (v - x);
        run += __shfl_sync(0xffffffffu, v, 31);
    }
}

__global__ void k_scan3() {
    int g = blockIdx.x * blockDim.x + threadIdx.x;
    if (g < Nn) {
        int o = g_offsets[g] + g_bsum[g >> 10];
        g_offsets[g] = o;
        g_cursor[g] = o;
    }
    if (g == 0) g_offsets[Nn] = NE_TOT;
}

__global__ void k_fill(const void* __restrict__ ei) {
    int t = blockIdx.x * blockDim.x + threadIdx.x;
    if (t >= NE_TOT) return;
    if (t < Ee) {
        int is64 = g_is64;
        int src = load_idx(ei, (size_t)t, is64);
        int dst = load_idx(ei, (size_t)Ee + t, is64);
        if ((unsigned)src < (unsigned)Nn && (unsigned)dst < (unsigned)Nn) {
            int pos = atomicAdd(&g_cursor[dst], 1);
            if ((unsigned)pos < (unsigned)NE_TOT) g_col[pos] = src;
        }
    } else {
        int i = t - Ee;
        int pos = atomicAdd(&g_cursor[i], 1);
        if ((unsigned)pos < (unsigned)NE_TOT) g_col[pos] = i;   // self loop
    }
}

// ============================ GEMM 1: x[N,512] @ W1[512,64] =================
// block tile 128 rows x 64 cols, 128 threads, thread tile 8x8, FFMA2 packed.
__global__ __launch_bounds__(128) void k_gemm1(const float* __restrict__ x,
                                               const float* __restrict__ W) {
    __shared__ float As[32][132];
    __shared__ float Bs[32][68];

    int tid = threadIdx.x;
    int row0 = blockIdx.x * 128;
    int ry = tid >> 3;      // 0..15 -> rows ry*8..+7
    int cx = tid & 7;       // 0..7  -> cols cx*8..+7

    unsigned long long acc[8][4];
#pragma unroll
    for (int r = 0; r < 8; r++)
#pragma unroll
        for (int c = 0; c < 4; c++) acc[r][c] = 0ull;

    for (int k0 = 0; k0 < IN_CH; k0 += 32) {
#pragma unroll
        for (int it = 0; it < 8; it++) {
            int s = it * 128 + tid;
            int r = s >> 3;
            int kq = s & 7;
            int grow = row0 + r;
            float4 v = make_float4(0.f, 0.f, 0.f, 0.f);
            if (grow < Nn)
                v = *reinterpret_cast<const float4*>(x + (size_t)grow * IN_CH + k0 + kq * 4);
            As[kq * 4 + 0][r] = v.x;
            As[kq * 4 + 1][r] = v.y;
            As[kq * 4 + 2][r] = v.z;
            As[kq * 4 + 3][r] = v.w;
        }
#pragma unroll
        for (int it = 0; it < 4; it++) {
            int s = it * 128 + tid;
            int kk = s >> 4;
            int cq = s & 15;
            float4 v = *reinterpret_cast<const float4*>(W + (size_t)(k0 + kk) * F1 + cq * 4);
            *reinterpret_cast<float4*>(&Bs[kk][cq * 4]) = v;
        }
        __syncthreads();

#pragma unroll 8
        for (int k = 0; k < 32; k++) {
            float4 a0 = *reinterpret_cast<const float4*>(&As[k][ry * 8]);
            float4 a1 = *reinterpret_cast<const float4*>(&As[k][ry * 8 + 4]);
            float4 b0 = *reinterpret_cast<const float4*>(&Bs[k][cx * 8]);
            float4 b1 = *reinterpret_cast<const float4*>(&Bs[k][cx * 8 + 4]);
            unsigned long long bp[4] = { pack2(b0.x, b0.y), pack2(b0.z, b0.w),
                                         pack2(b1.x, b1.y), pack2(b1.z, b1.w) };
            float av[8] = {a0.x, a0.y, a0.z, a0.w, a1.x, a1.y, a1.z, a1.w};
#pragma unroll
            for (int r = 0; r < 8; r++) {
                unsigned long long ap = pack2(av[r], av[r]);
#pragma unroll
                for (int c = 0; c < 4; c++) ffma2(acc[r][c], ap, bp[c]);
            }
        }
        __syncthreads();
    }

#pragma unroll
    for (int r = 0; r < 8; r++) {
        int grow = row0 + ry * 8 + r;
        if (grow < Nn) {
            float o[8];
#pragma unroll
            for (int c = 0; c < 4; c++) unpack2(acc[r][c], o[c * 2], o[c * 2 + 1]);
            float* dst = &g_h1[(size_t)grow * F1 + cx * 8];
            *reinterpret_cast<float4*>(dst)     = make_float4(o[0], o[1], o[2], o[3]);
            *reinterpret_cast<float4*>(dst + 4) = make_float4(o[4], o[5], o[6], o[7]);
        }
    }
}

// ============================ GEMM 2: h1act[N,64] @ W2[64,128] ==============
__global__ void k_gemm2(const float* __restrict__ W) {
    __shared__ float As[64][65];
    __shared__ float Bs[32][132];

    int tid = threadIdx.x;
    int row0 = blockIdx.x * 64;
    int ry = tid >> 4;
    int cx = tid & 15;

#pragma unroll
    for (int it = 0; it < 4; it++) {
        int s = it * 256 + tid;
        int r = s >> 4;
        int kq = s & 15;
        int grow = row0 + r;
        float4 v = make_float4(0.f, 0.f, 0.f, 0.f);
        if (grow < Nn)
            v = *reinterpret_cast<const float4*>(&g_h1act[(size_t)grow * F1 + kq * 4]);
        As[kq * 4 + 0][r] = v.x;
        As[kq * 4 + 1][r] = v.y;
        As[kq * 4 + 2][r] = v.z;
        As[kq * 4 + 3][r] = v.w;
    }

    float acc[4][8];
#pragma unroll
    for (int r = 0; r < 4; r++)
#pragma unroll
        for (int c = 0; c < 8; c++) acc[r][c] = 0.f;

    for (int kc = 0; kc < 64; kc += 32) {
#pragma unroll
        for (int it = 0; it < 4; it++) {
            int s = it * 256 + tid;
            int kk = s >> 5;
            int cq = s & 31;
            float4 v = *reinterpret_cast<const float4*>(W + (size_t)(kc + kk) * F2 + cq * 4);
            *reinterpret_cast<float4*>(&Bs[kk][cq * 4]) = v;
        }
        __syncthreads();

#pragma unroll
        for (int k = 0; k < 32; k++) {
            float a[4];
#pragma unroll
            for (int j = 0; j < 4; j++) a[j] = As[kc + k][ry * 4 + j];
            float4 b0 = *reinterpret_cast<const float4*>(&Bs[k][cx * 8]);
            float4 b1 = *reinterpret_cast<const float4*>(&Bs[k][cx * 8 + 4]);
            float b[8] = {b0.x, b0.y, b0.z, b0.w, b1.x, b1.y, b1.z, b1.w};
#pragma unroll
            for (int r = 0; r < 4; r++)
#pragma unroll
                for (int c = 0; c < 8; c++) acc[r][c] = fmaf(a[r], b[c], acc[r][c]);
        }
        __syncthreads();
    }

#pragma unroll
    for (int r = 0; r < 4; r++) {
        int grow = row0 + ry * 4 + r;
        if (grow < Nn) {
            float4 v0 = make_float4(acc[r][0], acc[r][1], acc[r][2], acc[r][3]);
            float4 v1 = make_float4(acc[r][4], acc[r][5], acc[r][6], acc[r][7]);
            *reinterpret_cast<float4*>(&g_h2[(size_t)grow * F2 + cx * 8]) = v0;
            *reinterpret_cast<float4*>(&g_h2[(size_t)grow * F2 + cx * 8 + 4]) = v1;
        }
    }
}

// ============================ fused edge softmax-aggregate ==================
// Lane-owns-head layout + software-pipelined gather: next edge's source row is
// loaded into a second register buffer while the current edge is processed.
template <int C, bool FINAL>
__global__ __launch_bounds__(256) void k_edge(const float* __restrict__ attl,
                                              const float* __restrict__ attr,
                                              const float* __restrict__ bias,
                                              float* __restrict__ outFinal) {
    constexpr int F = 8 * C;

    int warp = (blockIdx.x * blockDim.x + threadIdx.x) >> 5;
    int lane = threadIdx.x & 31;
    int sub  = lane >> 3;
    int head = lane & 7;
    int i = warp * 4 + sub;
    if (i >= Nn) return;

    const float* __restrict__ h = FINAL ? (const float*)g_h2 : (const float*)g_h1;

    float xi[C], wl[C], acc[C];
    float ar = 0.f;
    const float* hi = h + (size_t)i * F + head * C;
#pragma unroll
    for (int c4 = 0; c4 < C; c4 += 4) {
        float4 v = *reinterpret_cast<const float4*>(hi + c4);
        xi[c4 + 0] = v.x; xi[c4 + 1] = v.y; xi[c4 + 2] = v.z; xi[c4 + 3] = v.w;
    }
#pragma unroll
    for (int c = 0; c < C; c++) {
        wl[c] = attl[head * C + c];
        ar = fmaf(xi[c], attr[head * C + c], ar);
        acc[c] = 0.f;
    }

    int e0 = g_offsets[i];
    int e1 = g_offsets[i + 1];

    float m = __int_as_float(0xff800000);   // -inf
    float d = 0.f;

    // software pipeline: xjA = current row, xjB = next row (prefetched)
    float xjA[C];
    {
        int src0 = g_col[e0];
        const float* hj = h + (size_t)src0 * F + head * C;
#pragma unroll
        for (int c4 = 0; c4 < C; c4 += 4) {
            float4 v = *reinterpret_cast<const float4*>(hj + c4);
            xjA[c4 + 0] = v.x; xjA[c4 + 1] = v.y; xjA[c4 + 2] = v.z; xjA[c4 + 3] = v.w;
        }
    }

    for (int e = e0; e < e1; e++) {
        // prefetch next row (dup of current on last iteration; g_col is padded)
        int nidx = (e + 1 < e1) ? (e + 1) : e;
        int nsrc = g_col[nidx];
        float xjB[C];
        const float* hn = h + (size_t)nsrc * F + head * C;
#pragma unroll
        for (int c4 = 0; c4 < C; c4 += 4) {
            float4 v = *reinterpret_cast<const float4*>(hn + c4);
            xjB[c4 + 0] = v.x; xjB[c4 + 1] = v.y; xjB[c4 + 2] = v.z; xjB[c4 + 3] = v.w;
        }

        float lg = 0.f, al = 0.f;
#pragma unroll
        for (int c = 0; c < C; c++) {
            lg = fmaf(xi[c], xjA[c], lg);
            al = fmaf(wl[c], xjA[c], al);
        }
        float sig = 1.f / (1.f + __expf(-lg));
        float a = (al + ar) * sig;
        a = (a > 0.f) ? a : NEG_SLOPE * a;

        float mn = fmaxf(m, a);
        float corr = __expf(m - mn);          // 0 on first edge (m = -inf)
        float w = __expf(a - mn);
        d = d * corr + w;
#pragma unroll
        for (int c = 0; c < C; c++) acc[c] = fmaf(acc[c], corr, w * xjA[c]);
        m = mn;

#pragma unroll
        for (int c = 0; c < C; c++) xjA[c] = xjB[c];
    }

    float inv = 1.f / (d + 1e-16f);

    if constexpr (!FINAL) {
        float* o = g_h1act + (size_t)i * F + head * C;
#pragma unroll
        for (int c4 = 0; c4 < C; c4 += 4) {
            float v[4];
#pragma unroll
            for (int j = 0; j < 4; j++) {
                float t = acc[c4 + j] * inv + bias[head * C + c4 + j];
                v[j] = (t > 0.f) ? t : expm1f(t);
            }
            *reinterpret_cast<float4*>(o + c4) = make_float4(v[0], v[1], v[2], v[3]);
        }
    } else {
        float v[C];
#pragma unroll
        for (int c = 0; c < C; c++) {
            float s = acc[c] * inv;
            s += __shfl_xor_sync(0xffffffffu, s, 1);
            s += __shfl_xor_sync(0xffffffffu, s, 2);
            s += __shfl_xor_sync(0xffffffffu, s, 4);
            v[c] = s * 0.125f + bias[c];
        }
        if (head == 0) {
            float mx = v[0];
#pragma unroll
            for (int c = 1; c < C; c++) mx = fmaxf(mx, v[c]);
            float se = 0.f;
#pragma unroll
            for (int c = 0; c < C; c++) se += __expf(v[c] - mx);
            float lse = mx + logf(se);
            float* o = outFinal + (size_t)i * 16;
#pragma unroll
            for (int c4 = 0; c4 < C; c4 += 4)
                *reinterpret_cast<float4*>(o + c4) =
                    make_float4(v[c4] - lse, v[c4 + 1] - lse, v[c4 + 2] - lse, v[c4 + 3] - lse);
        }
    }
}

// ============================ launch ========================================
extern "C" void kernel_launch(void* const* d_in, const int* in_sizes, int n_in,
                              void* d_out, int out_size) {
    (void)in_sizes; (void)n_in; (void)out_size;
    const float* x     = (const float*)d_in[0];
    const void*  ei    = d_in[1];
    const float* W1    = (const float*)d_in[2];
    const float* attl1 = (const float*)d_in[3];
    const float* attr1 = (const float*)d_in[4];
    const float* b1    = (const float*)d_in[5];
    const float* W2    = (const float*)d_in[6];
    const float* attl2 = (const float*)d_in[7];
    const float* attr2 = (const float*)d_in[8];
    const float* b2    = (const float*)d_in[9];
    float* out = (float*)d_out;

    // NOTE: k_gemm1 is placed at launch index 3 — the slot ncu's -s 5 -c 1
    // empirically captures — so the next profile shows the heavy kernel.
    k_detect<<<1, 1>>>(ei);                               // 0
    k_init_count<<<(Nn + 255) / 256, 256>>>();            // 1
    k_count<<<(Ee + 255) / 256, 256>>>(ei);               // 2
    k_gemm1<<<(Nn + 127) / 128, 128>>>(x, W1);            // 3  (independent of CSR)
    k_scan1<<<98, 256>>>();                               // 4
    k_scan2<<<1, 32>>>();                                 // 5
    k_scan3<<<(Nn + 255) / 256, 256>>>();                 // 6
    k_fill<<<(NE_TOT + 255) / 256, 256>>>(ei);            // 7

    // Layer 1 aggregate
    k_edge<8, false><<<(Nn + 31) / 32, 256>>>(attl1, attr1, b1, nullptr);

    // Layer 2
    k_gemm2<<<(Nn + 63) / 64, 256>>>(W2);
    k_edge<16, true><<<(Nn + 31) / 32, 256>>>(attl2, attr2, b2, out);
}

// round 10
// speedup vs baseline: 1.2162x; 1.1059x over previous
#include <cuda_runtime.h>
#include <math.h>
#include <stdint.h>

// Problem constants (fixed by the dataset)
#define Nn 100000
#define Ee 1600000
#define NE_TOT (Ee + Nn)          // edges + self loops
#define F1 64                     // heads*hid  (8*8)
#define F2 128                    // heads*out  (8*16)
#define IN_CH 512
#define NEG_SLOPE 0.2f

// ---------------- device scratch (static allocation: allowed) ----------------
__device__ int   g_is64;          // 1 if edge_index is int64, 0 if int32
__device__ int   g_count[Nn];
__device__ int   g_offsets[Nn + 1];
__device__ int   g_bsum[128];
__device__ int   g_cursor[Nn];
__device__ int   g_col[NE_TOT + 8];   // +8 pad: prefetch-safe
__device__ __align__(16) float g_h1[(size_t)Nn * F1];     // gemm1 output
__device__ __align__(16) float g_h1act[(size_t)Nn * F1];  // layer1 aggregated + elu
__device__ __align__(16) float g_h2[(size_t)Nn * F2];     // gemm2 output

// ---------------- packed fp32x2 helpers (Blackwell FFMA2) -------------------
__device__ __forceinline__ unsigned long long pack2(float lo, float hi) {
    unsigned long long r;
    asm("mov.b64 %0, {%1, %2};" : "=l"(r) : "f"(lo), "f"(hi));
    return r;
}
__device__ __forceinline__ void ffma2(unsigned long long &d, unsigned long long a,
                                      unsigned long long b) {
    asm("fma.rn.f32x2 %0, %1, %2, %0;" : "+l"(d) : "l"(a), "l"(b));
}
__device__ __forceinline__ void unpack2(unsigned long long v, float &lo, float &hi) {
    asm("mov.b64 {%0, %1}, %2;" : "=f"(lo), "=f"(hi) : "l"(v));
}

// ============================ dtype detection ===============================
__global__ void k_detect(const void* ei) {
    const long long* p = (const long long*)ei;
    int ok = 1;
    for (int i = 0; i < 64; i++) {
        long long v = p[i];
        if (v < 0 || v >= Nn) { ok = 0; break; }
    }
    g_is64 = ok;
}

__device__ __forceinline__ int load_idx(const void* ei, size_t pos, int is64) {
    return is64 ? (int)((const long long*)ei)[pos] : ((const int*)ei)[pos];
}

// ============================ CSR build =====================================
__global__ void k_init_count() {
    int i = blockIdx.x * blockDim.x + threadIdx.x;
    if (i < Nn) g_count[i] = 1;   // self loop
}

__global__ void k_count(const void* __restrict__ ei) {
    int e = blockIdx.x * blockDim.x + threadIdx.x;
    if (e < Ee) {
        int is64 = g_is64;
        int dst = load_idx(ei, (size_t)Ee + e, is64);
        if ((unsigned)dst < (unsigned)Nn)
            atomicAdd(&g_count[dst], 1);
    }
}

__global__ void k_scan1() {
    __shared__ int warpsum[8];
    int t = threadIdx.x;
    int lane = t & 31;
    int wid = t >> 5;
    int base = blockIdx.x * 1024 + t * 4;

    int c0 = (base + 0 < Nn) ? g_count[base + 0] : 0;
    int c1 = (base + 1 < Nn) ? g_count[base + 1] : 0;
    int c2 = (base + 2 < Nn) ? g_count[base + 2] : 0;
    int c3 = (base + 3 < Nn) ? g_count[base + 3] : 0;
    int tot = c0 + c1 + c2 + c3;

    int v = tot;
#pragma unroll
    for (int off = 1; off < 32; off <<= 1) {
        int n = __shfl_up_sync(0xffffffffu, v, off);
        if (lane >= off) v += n;
    }
    if (lane == 31) warpsum[wid] = v;
    __syncthreads();
    if (t == 0) {
        int run = 0;
#pragma unroll
        for (int i = 0; i < 8; i++) { int x = warpsum[i]; warpsum[i] = run; run += x; }
    }
    __syncthreads();

    int exc = warpsum[wid] + (v - tot);
    if (base + 0 < Nn) g_offsets[base + 0] = exc;
    exc += c0;
    if (base + 1 < Nn) g_offsets[base + 1] = exc;
    exc += c1;
    if (base + 2 < Nn) g_offsets[base + 2] = exc;
    exc += c2;
    if (base + 3 < Nn) g_offsets[base + 3] = exc;

    if (t == 255) g_bsum[blockIdx.x] = warpsum[7] + v;
}

__global__ void k_scan2() {
    int lane = threadIdx.x;   // <<<1,32>>>
    int run = 0;
#pragma unroll
    for (int c = 0; c < 4; c++) {
        int idx = c * 32 + lane;
        int x = (idx < 98) ? g_bsum[idx] : 0;
        int v = x;
#pragma unroll
        for (int off = 1; off < 32; off <<= 1) {
            int n = __shfl_up_sync(0xffffffffu, v, off);
            if (lane >= off) v += n;
        }
        if (idx < 98) g_bsum[idx] = run + (v - x);
        run += __shfl_sync(0xffffffffu, v, 31);
    }
}

__global__ void k_scan3() {
    int g = blockIdx.x * blockDim.x + threadIdx.x;
    if (g < Nn) {
        int o = g_offsets[g] + g_bsum[g >> 10];
        g_offsets[g] = o;
        g_cursor[g] = o;
    }
    if (g == 0) g_offsets[Nn] = NE_TOT;
}

__global__ void k_fill(const void* __restrict__ ei) {
    int t = blockIdx.x * blockDim.x + threadIdx.x;
    if (t >= NE_TOT) return;
    if (t < Ee) {
        int is64 = g_is64;
        int src = load_idx(ei, (size_t)t, is64);
        int dst = load_idx(ei, (size_t)Ee + t, is64);
        if ((unsigned)src < (unsigned)Nn && (unsigned)dst < (unsigned)Nn) {
            int pos = atomicAdd(&g_cursor[dst], 1);
            if ((unsigned)pos < (unsigned)NE_TOT) g_col[pos] = src;
        }
    } else {
        int i = t - Ee;
        int pos = atomicAdd(&g_cursor[i], 1);
        if ((unsigned)pos < (unsigned)NE_TOT) g_col[pos] = i;   // self loop
    }
}

// ============================ GEMM 1: x[N,512] @ W1[512,64] =================
// 128 rows x 64 cols per block, 128 threads, 8x8 thread tile, FFMA2.
// Conflict-free smem: A row-major [128][36] (direct float4 store/load),
// B cols remapped to {4cx, 32+4cx} so b-load bank-quads are (k+cx)%8 distinct.
__global__ __launch_bounds__(128) void k_gemm1(const float* __restrict__ x,
                                               const float* __restrict__ W) {
    __shared__ float As[128][36];   // row-major, pad 36 (144 B rows, 16B aligned)
    __shared__ float Bs[32][68];    // [k][col], pad 68

    int tid = threadIdx.x;
    int row0 = blockIdx.x * 128;
    int ry = tid >> 3;      // 0..15 -> rows ry*8..+7
    int cx = tid & 7;       // cols {4cx..4cx+3} and {32+4cx..+3}

    unsigned long long acc[8][4];   // [row][pair]; pairs 0,1 -> cols 4cx..; 2,3 -> 32+4cx..
#pragma unroll
    for (int r = 0; r < 8; r++)
#pragma unroll
        for (int c = 0; c < 4; c++) acc[r][c] = 0ull;

    for (int k0 = 0; k0 < IN_CH; k0 += 32) {
        // A tile: direct float4 store, row-major. quad=(r+kq)%8, 4-fold -> conflict-free
#pragma unroll
        for (int it = 0; it < 8; it++) {
            int s = it * 128 + tid;
            int r = s >> 3;              // 0..127
            int kq = s & 7;              // x4 floats
            int grow = row0 + r;
            float4 v = make_float4(0.f, 0.f, 0.f, 0.f);
            if (grow < Nn)
                v = *reinterpret_cast<const float4*>(x + (size_t)grow * IN_CH + k0 + kq * 4);
            *reinterpret_cast<float4*>(&As[r][kq * 4]) = v;
        }
        // B tile: quad=(kk+cq)%8, 4-fold -> conflict-free
#pragma unroll
        for (int it = 0; it < 4; it++) {
            int s = it * 128 + tid;
            int kk = s >> 4;             // 0..31
            int cq = s & 15;
            float4 v = *reinterpret_cast<const float4*>(W + (size_t)(k0 + kk) * F1 + cq * 4);
            *reinterpret_cast<float4*>(&Bs[kk][cq * 4]) = v;
        }
        __syncthreads();

#pragma unroll
        for (int k4 = 0; k4 < 8; k4++) {
            // load 8 rows x 4 k's of A (float4 along k, broadcast across lanes)
            float4 a4[8];
#pragma unroll
            for (int j = 0; j < 8; j++)
                a4[j] = *reinterpret_cast<const float4*>(&As[ry * 8 + j][k4 * 4]);
#pragma unroll
            for (int t = 0; t < 4; t++) {
                int k = k4 * 4 + t;
                float4 b0 = *reinterpret_cast<const float4*>(&Bs[k][cx * 4]);
                float4 b1 = *reinterpret_cast<const float4*>(&Bs[k][32 + cx * 4]);
                unsigned long long bp[4] = { pack2(b0.x, b0.y), pack2(b0.z, b0.w),
                                             pack2(b1.x, b1.y), pack2(b1.z, b1.w) };
#pragma unroll
                for (int j = 0; j < 8; j++) {
                    float av = (t == 0) ? a4[j].x : (t == 1) ? a4[j].y
                             : (t == 2) ? a4[j].z : a4[j].w;
                    unsigned long long ap = pack2(av, av);
#pragma unroll
                    for (int c = 0; c < 4; c++) ffma2(acc[j][c], ap, bp[c]);
                }
            }
        }
        __syncthreads();
    }

#pragma unroll
    for (int r = 0; r < 8; r++) {
        int grow = row0 + ry * 8 + r;
        if (grow < Nn) {
            float o[8];
#pragma unroll
            for (int c = 0; c < 4; c++) unpack2(acc[r][c], o[c * 2], o[c * 2 + 1]);
            float* dst = &g_h1[(size_t)grow * F1];
            *reinterpret_cast<float4*>(dst + cx * 4)      = make_float4(o[0], o[1], o[2], o[3]);
            *reinterpret_cast<float4*>(dst + 32 + cx * 4) = make_float4(o[4], o[5], o[6], o[7]);
        }
    }
}

// ============================ GEMM 2: h1act[N,64] @ W2[64,128] ==============
// cols remapped to {4cx, 64+4cx} -> conflict-free b loads (quad=(k+cx)%8).
__global__ void k_gemm2(const float* __restrict__ W) {
    __shared__ float As[64][65];
    __shared__ float Bs[32][132];

    int tid = threadIdx.x;
    int row0 = blockIdx.x * 64;
    int ry = tid >> 4;   // 0..15 -> rows ry*4..+3
    int cx = tid & 15;   // cols {4cx..} and {64+4cx..}

#pragma unroll
    for (int it = 0; it < 4; it++) {
        int s = it * 256 + tid;
        int r = s >> 4;
        int kq = s & 15;
        int grow = row0 + r;
        float4 v = make_float4(0.f, 0.f, 0.f, 0.f);
        if (grow < Nn)
            v = *reinterpret_cast<const float4*>(&g_h1act[(size_t)grow * F1 + kq * 4]);
        As[kq * 4 + 0][r] = v.x;
        As[kq * 4 + 1][r] = v.y;
        As[kq * 4 + 2][r] = v.z;
        As[kq * 4 + 3][r] = v.w;
    }

    float acc[4][8];
#pragma unroll
    for (int r = 0; r < 4; r++)
#pragma unroll
        for (int c = 0; c < 8; c++) acc[r][c] = 0.f;

    for (int kc = 0; kc < 64; kc += 32) {
#pragma unroll
        for (int it = 0; it < 4; it++) {
            int s = it * 256 + tid;
            int kk = s >> 5;
            int cq = s & 31;
            float4 v = *reinterpret_cast<const float4*>(W + (size_t)(kc + kk) * F2 + cq * 4);
            *reinterpret_cast<float4*>(&Bs[kk][cq * 4]) = v;
        }
        __syncthreads();

#pragma unroll
        for (int k = 0; k < 32; k++) {
            float a[4];
#pragma unroll
            for (int j = 0; j < 4; j++) a[j] = As[kc + k][ry * 4 + j];
            float4 b0 = *reinterpret_cast<const float4*>(&Bs[k][cx * 4]);
            float4 b1 = *reinterpret_cast<const float4*>(&Bs[k][64 + cx * 4]);
            float b[8] = {b0.x, b0.y, b0.z, b0.w, b1.x, b1.y, b1.z, b1.w};
#pragma unroll
            for (int r = 0; r < 4; r++)
#pragma unroll
                for (int c = 0; c < 8; c++) acc[r][c] = fmaf(a[r], b[c], acc[r][c]);
        }
        __syncthreads();
    }

#pragma unroll
    for (int r = 0; r < 4; r++) {
        int grow = row0 + ry * 4 + r;
        if (grow < Nn) {
            float* dst = &g_h2[(size_t)grow * F2];
            *reinterpret_cast<float4*>(dst + cx * 4) =
                make_float4(acc[r][0], acc[r][1], acc[r][2], acc[r][3]);
            *reinterpret_cast<float4*>(dst + 64 + cx * 4) =
                make_float4(acc[r][4], acc[r][5], acc[r][6], acc[r][7]);
        }
    }
}

// ============================ fused edge softmax-aggregate ==================
template <int C, bool FINAL>
__global__ __launch_bounds__(256) void k_edge(const float* __restrict__ attl,
                                              const float* __restrict__ attr,
                                              const float* __restrict__ bias,
                                              float* __restrict__ outFinal) {
    constexpr int F = 8 * C;

    int warp = (blockIdx.x * blockDim.x + threadIdx.x) >> 5;
    int lane = threadIdx.x & 31;
    int sub  = lane >> 3;
    int head = lane & 7;
    int i = warp * 4 + sub;
    if (i >= Nn) return;

    const float* __restrict__ h = FINAL ? (const float*)g_h2 : (const float*)g_h1;

    float xi[C], wl[C], acc[C];
    float ar = 0.f;
    const float* hi = h + (size_t)i * F + head * C;
#pragma unroll
    for (int c4 = 0; c4 < C; c4 += 4) {
        float4 v = *reinterpret_cast<const float4*>(hi + c4);
        xi[c4 + 0] = v.x; xi[c4 + 1] = v.y; xi[c4 + 2] = v.z; xi[c4 + 3] = v.w;
    }
#pragma unroll
    for (int c = 0; c < C; c++) {
        wl[c] = attl[head * C + c];
        ar = fmaf(xi[c], attr[head * C + c], ar);
        acc[c] = 0.f;
    }

    int e0 = g_offsets[i];
    int e1 = g_offsets[i + 1];

    float m = __int_as_float(0xff800000);   // -inf
    float d = 0.f;

    float xjA[C];
    {
        int src0 = g_col[e0];
        const float* hj = h + (size_t)src0 * F + head * C;
#pragma unroll
        for (int c4 = 0; c4 < C; c4 += 4) {
            float4 v = *reinterpret_cast<const float4*>(hj + c4);
            xjA[c4 + 0] = v.x; xjA[c4 + 1] = v.y; xjA[c4 + 2] = v.z; xjA[c4 + 3] = v.w;
        }
    }

    for (int e = e0; e < e1; e++) {
        int nsrc = g_col[e + 1];          // g_col padded: safe at e1
        float xjB[C];
        const float* hn = h + (size_t)nsrc * F + head * C;
#pragma unroll
        for (int c4 = 0; c4 < C; c4 += 4) {
            float4 v = *reinterpret_cast<const float4*>(hn + c4);
            xjB[c4 + 0] = v.x; xjB[c4 + 1] = v.y; xjB[c4 + 2] = v.z; xjB[c4 + 3] = v.w;
        }

        float lg = 0.f, al = 0.f;
#pragma unroll
        for (int c = 0; c < C; c++) {
            lg = fmaf(xi[c], xjA[c], lg);
            al = fmaf(wl[c], xjA[c], al);
        }
        float sig = 1.f / (1.f + __expf(-lg));
        float a = (al + ar) * sig;
        a = (a > 0.f) ? a : NEG_SLOPE * a;

        float mn = fmaxf(m, a);
        float corr = __expf(m - mn);
        float w = __expf(a - mn);
        d = d * corr + w;
#pragma unroll
        for (int c = 0; c < C; c++) acc[c] = fmaf(acc[c], corr, w * xjA[c]);
        m = mn;

#pragma unroll
        for (int c = 0; c < C; c++) xjA[c] = xjB[c];
    }

    float inv = 1.f / (d + 1e-16f);

    if constexpr (!FINAL) {
        float* o = g_h1act + (size_t)i * F + head * C;
#pragma unroll
        for (int c4 = 0; c4 < C; c4 += 4) {
            float v[4];
#pragma unroll
            for (int j = 0; j < 4; j++) {
                float t = acc[c4 + j] * inv + bias[head * C + c4 + j];
                v[j] = (t > 0.f) ? t : expm1f(t);
            }
            *reinterpret_cast<float4*>(o + c4) = make_float4(v[0], v[1], v[2], v[3]);
        }
    } else {
        float v[C];
#pragma unroll
        for (int c = 0; c < C; c++) {
            float s = acc[c] * inv;
            s += __shfl_xor_sync(0xffffffffu, s, 1);
            s += __shfl_xor_sync(0xffffffffu, s, 2);
            s += __shfl_xor_sync(0xffffffffu, s, 4);
            v[c] = s * 0.125f + bias[c];
        }
        if (head == 0) {
            float mx = v[0];
#pragma unroll
            for (int c = 1; c < C; c++) mx = fmaxf(mx, v[c]);
            float se = 0.f;
#pragma unroll
            for (int c = 0; c < C; c++) se += __expf(v[c] - mx);
            float lse = mx + logf(se);
            float* o = outFinal + (size_t)i * 16;
#pragma unroll
            for (int c4 = 0; c4 < C; c4 += 4)
                *reinterpret_cast<float4*>(o + c4) =
                    make_float4(v[c4] - lse, v[c4 + 1] - lse, v[c4 + 2] - lse, v[c4 + 3] - lse);
        }
    }
}

// ============================ launch ========================================
extern "C" void kernel_launch(void* const* d_in, const int* in_sizes, int n_in,
                              void* d_out, int out_size) {
    (void)in_sizes; (void)n_in; (void)out_size;
    const float* x     = (const float*)d_in[0];
    const void*  ei    = d_in[1];
    const float* W1    = (const float*)d_in[2];
    const float* attl1 = (const float*)d_in[3];
    const float* attr1 = (const float*)d_in[4];
    const float* b1    = (const float*)d_in[5];
    const float* W2    = (const float*)d_in[6];
    const float* attl2 = (const float*)d_in[7];
    const float* attr2 = (const float*)d_in[8];
    const float* b2    = (const float*)d_in[9];
    float* out = (float*)d_out;

    // k_gemm1 stays at launch index 3 (the slot ncu captures).
    k_detect<<<1, 1>>>(ei);                               // 0
    k_init_count<<<(Nn + 255) / 256, 256>>>();            // 1
    k_count<<<(Ee + 255) / 256, 256>>>(ei);               // 2
    k_gemm1<<<(Nn + 127) / 128, 128>>>(x, W1);            // 3
    k_scan1<<<98, 256>>>();                               // 4
    k_scan2<<<1, 32>>>();                                 // 5
    k_scan3<<<(Nn + 255) / 256, 256>>>();                 // 6
    k_fill<<<(NE_TOT + 255) / 256, 256>>>(ei);            // 7

    // Layer 1 aggregate
    k_edge<8, false><<<(Nn + 31) / 32, 256>>>(attl1, attr1, b1, nullptr);

    // Layer 2
    k_gemm2<<<(Nn + 63) / 64, 256>>>(W2);
    k_edge<16, true><<<(Nn + 31) / 32, 256>>>(attl2, attr2, b2, out);
}